// round 9
// baseline (speedup 1.0000x reference)
#include <cuda_runtime.h>
#include <math.h>

#define BZ 2
#define TSEQ 2048
#define DM 1024
#define NH 16
#define DH 64
#define DFF 4096
#define NROWS (BZ * TSEQ)   /* 4096 */

// ---------------- scratch (device globals; no allocation allowed) ----------
__device__ float g_hn [(size_t)NROWS * DM];
__device__ float g_q  [(size_t)NROWS * DM];
__device__ float g_k  [(size_t)NROWS * DM];
__device__ float g_v  [(size_t)NROWS * DM];
__device__ float g_ctx[(size_t)NROWS * DM];
__device__ float g_x1 [(size_t)NROWS * DM];
__device__ float g_ff [(size_t)NROWS * DFF];
// tf32-rounded weights
__device__ float g_wq [(size_t)DM * DM];
__device__ float g_wk [(size_t)DM * DM];
__device__ float g_wv [(size_t)DM * DM];
__device__ float g_wo [(size_t)DM * DM];
__device__ float g_w1 [(size_t)DFF * DM];
__device__ float g_w2 [(size_t)DM * DFF];

// ---------------- helpers --------------------------------------------------
__device__ __forceinline__ unsigned f2tf(float x)
{
    unsigned u;
    asm("cvt.rna.tf32.f32 %0, %1;" : "=r"(u) : "f"(x));
    return u;
}
__device__ __forceinline__ float f2tff(float x) { return __uint_as_float(f2tf(x)); }

__device__ __forceinline__ void mma_tf32(float c[4], const unsigned a[4], const unsigned b[2])
{
    asm volatile(
        "mma.sync.aligned.m16n8k8.row.col.f32.tf32.tf32.f32 "
        "{%0,%1,%2,%3}, {%4,%5,%6,%7}, {%8,%9}, {%0,%1,%2,%3};\n"
        : "+f"(c[0]), "+f"(c[1]), "+f"(c[2]), "+f"(c[3])
        : "r"(a[0]), "r"(a[1]), "r"(a[2]), "r"(a[3]), "r"(b[0]), "r"(b[1]));
}

__device__ __forceinline__ void cp16(unsigned dst, const void* src)
{
    asm volatile("cp.async.cg.shared.global [%0], [%1], 16;\n" :: "r"(dst), "l"(src));
}
__device__ __forceinline__ void cp_commit() { asm volatile("cp.async.commit_group;\n"); }
template<int N>
__device__ __forceinline__ void cp_wait() { asm volatile("cp.async.wait_group %0;\n" :: "n"(N)); }

// ---------------- weight pre-rounding (rna to tf32) ------------------------
__global__ void round_w(const float* __restrict__ src, float* __restrict__ dst, int n4)
{
    int i = blockIdx.x * 256 + threadIdx.x;
    if (i >= n4) return;
    float4 v = ((const float4*)src)[i];
    v.x = f2tff(v.x); v.y = f2tff(v.y); v.z = f2tff(v.z); v.w = f2tff(v.w);
    ((float4*)dst)[i] = v;
}

// ---------------- layernorm: one block per row, 256 threads ---------------
// output rounded to tf32 (rna) — it is only ever consumed as GEMM A.
__global__ void ln_kernel(const float* __restrict__ x,
                          const float* __restrict__ gam,
                          const float* __restrict__ bet,
                          float* __restrict__ y)
{
    int row = blockIdx.x;
    int tid = threadIdx.x;
    const float4* xr = (const float4*)(x + (size_t)row * DM);
    float4 v = xr[tid];

    __shared__ float sh[8];
    __shared__ float bc[2];

    float s = v.x + v.y + v.z + v.w;
    #pragma unroll
    for (int o = 16; o > 0; o >>= 1) s += __shfl_xor_sync(0xffffffffu, s, o);
    if ((tid & 31) == 0) sh[tid >> 5] = s;
    __syncthreads();
    if (tid == 0) {
        float t = 0.f;
        #pragma unroll
        for (int i = 0; i < 8; i++) t += sh[i];
        bc[0] = t * (1.0f / DM);
    }
    __syncthreads();
    float mu = bc[0];

    float4 d = make_float4(v.x - mu, v.y - mu, v.z - mu, v.w - mu);
    float sq = d.x * d.x + d.y * d.y + d.z * d.z + d.w * d.w;
    #pragma unroll
    for (int o = 16; o > 0; o >>= 1) sq += __shfl_xor_sync(0xffffffffu, sq, o);
    __syncthreads();
    if ((tid & 31) == 0) sh[tid >> 5] = sq;
    __syncthreads();
    if (tid == 0) {
        float t = 0.f;
        #pragma unroll
        for (int i = 0; i < 8; i++) t += sh[i];
        bc[1] = rsqrtf(t * (1.0f / DM) + 1e-5f);
    }
    __syncthreads();
    float rstd = bc[1];

    float4 gv = ((const float4*)gam)[tid];
    float4 bv = ((const float4*)bet)[tid];
    float4 o4;
    o4.x = f2tff(d.x * rstd * gv.x + bv.x);
    o4.y = f2tff(d.y * rstd * gv.y + bv.y);
    o4.z = f2tff(d.z * rstd * gv.z + bv.z);
    o4.w = f2tff(d.w * rstd * gv.w + bv.w);
    ((float4*)(y + (size_t)row * DM))[tid] = o4;
}

// ---------------- tf32 GEMM-NT, 3-stage cp.async + frag double buffer -----
// C[N,O] = A[N,K] @ W[O,K]^T
// EPI: 0 = +bias, round tf32 (QKV)   1 = +bias+res (fp32 out)
//      2 = +bias+gelu, round tf32 (fc1)
// 128x128 tile, BK=32, 256 thr = 8 warps (2M x 4N), warp 64x32, m16n8k8.
#define GLDS 36
#define GBUF (128 * GLDS)
#define NSTG 3

template<int EPI>
__global__ void __launch_bounds__(256) gemm_tf32(const float* __restrict__ A,
                                                 const float* __restrict__ W,
                                                 const float* __restrict__ bias,
                                                 const float* __restrict__ res,
                                                 float* __restrict__ C,
                                                 int N, int O, int K)
{
    extern __shared__ unsigned smem_g[];
    unsigned* Ab = smem_g;                  // [NSTG][128][GLDS]
    unsigned* Wb = smem_g + NSTG * GBUF;

    int tid  = threadIdx.x;
    int warp = tid >> 5;
    int lane = tid & 31;
    int g = lane >> 2;
    int t = lane & 3;
    int m0  = (warp >> 2) * 64;
    int n0w = (warp & 3) * 32;
    int bn = blockIdx.y * 128;
    int bo = blockIdx.x * 128;

    float acc[4][4][4];
    #pragma unroll
    for (int mi = 0; mi < 4; mi++)
        #pragma unroll
        for (int nj = 0; nj < 4; nj++)
            #pragma unroll
            for (int c = 0; c < 4; c++) acc[mi][nj][c] = 0.f;

    unsigned abase = (unsigned)__cvta_generic_to_shared(Ab);
    unsigned wbase = (unsigned)__cvta_generic_to_shared(Wb);
    int lrow = tid >> 1;                  // 0..127
    int lcol = (tid & 1) * 16;            // 0 or 16 (floats)

    // COVERAGE FIX: each thread must copy 16 contiguous floats = 4 x cp16
    // at word offsets lcol + {0,4,8,12}. (The failing version issued only
    // 2 cp16 at +0,+8, leaving half of every k-slice unwritten.)
    #define STAGE_LOAD(s, k0)                                                   \
    {                                                                           \
        _Pragma("unroll")                                                       \
        for (int i = 0; i < 4; i++) {                                           \
            unsigned off = ((s) * GBUF + lrow * GLDS + lcol + i * 4) * 4u;      \
            cp16(abase + off, A + (size_t)(bn + lrow) * K + (k0) + lcol + i * 4); \
            cp16(wbase + off, W + (size_t)(bo + lrow) * K + (k0) + lcol + i * 4); \
        }                                                                       \
        cp_commit();                                                            \
    }

    STAGE_LOAD(0, 0)
    STAGE_LOAD(1, 32)

    #define LOAD_FRAG(bi, As, Ws, ks)                                           \
    {                                                                           \
        _Pragma("unroll")                                                       \
        for (int mi = 0; mi < 4; mi++) {                                        \
            int r = m0 + mi * 16 + g;                                           \
            af[bi][mi][0] = As[r * GLDS + (ks) + t];                            \
            af[bi][mi][1] = As[(r + 8) * GLDS + (ks) + t];                      \
            af[bi][mi][2] = As[r * GLDS + (ks) + t + 4];                        \
            af[bi][mi][3] = As[(r + 8) * GLDS + (ks) + t + 4];                  \
        }                                                                       \
        _Pragma("unroll")                                                       \
        for (int nj = 0; nj < 4; nj++) {                                        \
            int r = n0w + nj * 8 + g;                                           \
            bf[bi][nj][0] = Ws[r * GLDS + (ks) + t];                            \
            bf[bi][nj][1] = Ws[r * GLDS + (ks) + t + 4];                        \
        }                                                                       \
    }

    int ktiles = K >> 5;
    for (int kt = 0; kt < ktiles; kt++) {
        // TAIL FIX: last iteration has only one group pending -> wait for 0.
        if (kt + 1 < ktiles) cp_wait<1>(); else cp_wait<0>();
        __syncthreads();
        if (kt + 2 < ktiles) {
            STAGE_LOAD((kt + 2) % NSTG, (kt + 2) * 32)
        }
        int s = kt % NSTG;
        const unsigned* As = Ab + s * GBUF;
        const unsigned* Ws = Wb + s * GBUF;

        unsigned af[2][4][4], bf[2][4][2];
        LOAD_FRAG(0, As, Ws, 0)
        #pragma unroll
        for (int ksi = 0; ksi < 4; ksi++) {
            if (ksi < 3) LOAD_FRAG((ksi + 1) & 1, As, Ws, (ksi + 1) * 8)
            int b = ksi & 1;
            #pragma unroll
            for (int mi = 0; mi < 4; mi++)
                #pragma unroll
                for (int nj = 0; nj < 4; nj++)
                    mma_tf32(acc[mi][nj], af[b][mi], bf[b][nj]);
        }
    }

    #pragma unroll
    for (int mi = 0; mi < 4; mi++) {
        #pragma unroll
        for (int rr = 0; rr < 2; rr++) {
            int n = bn + m0 + mi * 16 + g + rr * 8;
            #pragma unroll
            for (int nj = 0; nj < 4; nj++) {
                int o = bo + n0w + nj * 8 + t * 2;
                float c0 = acc[mi][nj][rr * 2 + 0] + bias[o];
                float c1 = acc[mi][nj][rr * 2 + 1] + bias[o + 1];
                if (EPI == 1) {
                    float2 rv = *(const float2*)(res + (size_t)n * O + o);
                    c0 += rv.x; c1 += rv.y;
                }
                if (EPI == 2) {
                    c0 = 0.5f * c0 * (1.0f + erff(c0 * 0.70710678118654752f));
                    c1 = 0.5f * c1 * (1.0f + erff(c1 * 0.70710678118654752f));
                }
                if (EPI == 0 || EPI == 2) { c0 = f2tff(c0); c1 = f2tff(c1); }
                *(float2*)(C + (size_t)n * O + o) = make_float2(c0, c1);
            }
        }
    }
}

// ---------------- FA2 attention, tf32 mma, 64x64 tiles, 128 threads -------
#define ALDS 68

__global__ void __launch_bounds__(128) attn_mma(const float* __restrict__ Q,
                                                const float* __restrict__ K,
                                                const float* __restrict__ V,
                                                float* __restrict__ O)
{
    extern __shared__ unsigned sm_a[];
    unsigned* Qs = sm_a;                    // [64][ALDS]
    unsigned* Ks = Qs + 64 * ALDS;
    unsigned* Vt = Ks + 64 * ALDS;          // transposed [d][key]
    unsigned* Ps = Vt + 64 * ALDS;          // [4][16][ALDS]

    int tid  = threadIdx.x;
    int warp = tid >> 5;
    int lane = tid & 31;
    int g = lane >> 2;
    int t = lane & 3;
    int qt = blockIdx.x, h = blockIdx.y, b = blockIdx.z;
    int q0 = qt * 64;
    int wm = warp * 16;

    {
        int r = tid >> 1, half = tid & 1;
        const float* Qb = Q + (size_t)(b * TSEQ + q0 + r) * DM + h * DH + half * 32;
        #pragma unroll
        for (int c = 0; c < 8; c++) {
            float4 v = *(const float4*)(Qb + c * 4);
            int d = half * 32 + c * 4;
            Qs[r * ALDS + d + 0] = __float_as_uint(v.x * 0.125f);
            Qs[r * ALDS + d + 1] = __float_as_uint(v.y * 0.125f);
            Qs[r * ALDS + d + 2] = __float_as_uint(v.z * 0.125f);
            Qs[r * ALDS + d + 3] = __float_as_uint(v.w * 0.125f);
        }
    }

    float mrow[2] = { -1e30f, -1e30f };
    float lrow[2] = { 0.f, 0.f };
    float o[8][4];
    #pragma unroll
    for (int nj = 0; nj < 8; nj++)
        #pragma unroll
        for (int c = 0; c < 4; c++) o[nj][c] = 0.f;

    for (int kt = 0; kt <= qt; kt++) {
        __syncthreads();
        {
            int kr = tid >> 1, half = tid & 1;
            const float* Kb = K + (size_t)(b * TSEQ + kt * 64 + kr) * DM + h * DH + half * 32;
            const float* Vb = V + (size_t)(b * TSEQ + kt * 64 + kr) * DM + h * DH + half * 32;
            #pragma unroll
            for (int c = 0; c < 8; c++) {
                float4 kv = *(const float4*)(Kb + c * 4);
                float4 vv = *(const float4*)(Vb + c * 4);
                int d = half * 32 + c * 4;
                Ks[kr * ALDS + d + 0] = __float_as_uint(kv.x);
                Ks[kr * ALDS + d + 1] = __float_as_uint(kv.y);
                Ks[kr * ALDS + d + 2] = __float_as_uint(kv.z);
                Ks[kr * ALDS + d + 3] = __float_as_uint(kv.w);
                Vt[(d + 0) * ALDS + kr] = __float_as_uint(vv.x);
                Vt[(d + 1) * ALDS + kr] = __float_as_uint(vv.y);
                Vt[(d + 2) * ALDS + kr] = __float_as_uint(vv.z);
                Vt[(d + 3) * ALDS + kr] = __float_as_uint(vv.w);
            }
        }
        __syncthreads();

        float s[8][4];
        #pragma unroll
        for (int nj = 0; nj < 8; nj++)
            #pragma unroll
            for (int c = 0; c < 4; c++) s[nj][c] = 0.f;

        #pragma unroll
        for (int ks = 0; ks < 8; ks++) {
            unsigned a[4];
            a[0] = Qs[(wm + g) * ALDS + ks * 8 + t];
            a[1] = Qs[(wm + g + 8) * ALDS + ks * 8 + t];
            a[2] = Qs[(wm + g) * ALDS + ks * 8 + t + 4];
            a[3] = Qs[(wm + g + 8) * ALDS + ks * 8 + t + 4];
            #pragma unroll
            for (int nj = 0; nj < 8; nj++) {
                unsigned bfr[2];
                bfr[0] = Ks[(nj * 8 + g) * ALDS + ks * 8 + t];
                bfr[1] = Ks[(nj * 8 + g) * ALDS + ks * 8 + t + 4];
                mma_tf32(s[nj], a, bfr);
            }
        }

        if (kt == qt) {
            #pragma unroll
            for (int nj = 0; nj < 8; nj++)
                #pragma unroll
                for (int c = 0; c < 4; c++) {
                    int col = nj * 8 + 2 * t + (c & 1);
                    int row = wm + g + ((c >> 1) << 3);
                    if (col > row) s[nj][c] = -1e30f;
                }
        }

        #pragma unroll
        for (int rr = 0; rr < 2; rr++) {
            float rm = -1e30f;
            #pragma unroll
            for (int nj = 0; nj < 8; nj++)
                rm = fmaxf(rm, fmaxf(s[nj][rr * 2], s[nj][rr * 2 + 1]));
            rm = fmaxf(rm, __shfl_xor_sync(0xffffffffu, rm, 1));
            rm = fmaxf(rm, __shfl_xor_sync(0xffffffffu, rm, 2));
            float mn = fmaxf(mrow[rr], rm);
            float alpha = __expf(mrow[rr] - mn);
            float rs = 0.f;
            int prow = wm * ALDS + (g + rr * 8) * ALDS;
            #pragma unroll
            for (int nj = 0; nj < 8; nj++) {
                float p0 = __expf(s[nj][rr * 2] - mn);
                float p1 = __expf(s[nj][rr * 2 + 1] - mn);
                Ps[prow + nj * 8 + 2 * t]     = f2tf(p0);
                Ps[prow + nj * 8 + 2 * t + 1] = f2tf(p1);
                rs += p0 + p1;
            }
            rs += __shfl_xor_sync(0xffffffffu, rs, 1);
            rs += __shfl_xor_sync(0xffffffffu, rs, 2);
            lrow[rr] = lrow[rr] * alpha + rs;
            mrow[rr] = mn;
            #pragma unroll
            for (int nj = 0; nj < 8; nj++) {
                o[nj][rr * 2]     *= alpha;
                o[nj][rr * 2 + 1] *= alpha;
            }
        }
        __syncwarp();

        #pragma unroll
        for (int ks = 0; ks < 8; ks++) {
            unsigned a[4];
            int pb = wm * ALDS;
            a[0] = Ps[pb + g * ALDS + ks * 8 + t];
            a[1] = Ps[pb + (g + 8) * ALDS + ks * 8 + t];
            a[2] = Ps[pb + g * ALDS + ks * 8 + t + 4];
            a[3] = Ps[pb + (g + 8) * ALDS + ks * 8 + t + 4];
            #pragma unroll
            for (int nj = 0; nj < 8; nj++) {
                unsigned bfr[2];
                bfr[0] = Vt[(nj * 8 + g) * ALDS + ks * 8 + t];
                bfr[1] = Vt[(nj * 8 + g) * ALDS + ks * 8 + t + 4];
                mma_tf32(o[nj], a, bfr);
            }
        }
    }

    #pragma unroll
    for (int rr = 0; rr < 2; rr++) {
        float inv = 1.0f / lrow[rr];
        int row = q0 + wm + g + rr * 8;
        float* Ob = O + (size_t)(b * TSEQ + row) * DM + h * DH;
        #pragma unroll
        for (int nj = 0; nj < 8; nj++) {
            float2 w = make_float2(f2tff(o[nj][rr * 2] * inv),
                                   f2tff(o[nj][rr * 2 + 1] * inv));
            *(float2*)(Ob + nj * 8 + 2 * t) = w;
        }
    }
}

// ---------------- launch -------------------------------------------------
extern "C" void kernel_launch(void* const* d_in, const int* in_sizes, int n_in,
                              void* d_out, int out_size)
{
    const float* x    = (const float*)d_in[0];
    // d_in[1] = causal mask (static, ignored)
    const float* wq_w = (const float*)d_in[2];
    const float* wq_b = (const float*)d_in[3];
    const float* wk_w = (const float*)d_in[4];
    const float* wk_b = (const float*)d_in[5];
    const float* wv_w = (const float*)d_in[6];
    const float* wv_b = (const float*)d_in[7];
    const float* wo_w = (const float*)d_in[8];
    const float* wo_b = (const float*)d_in[9];
    const float* fc1_w = (const float*)d_in[10];
    const float* fc1_b = (const float*)d_in[11];
    const float* fc2_w = (const float*)d_in[12];
    const float* fc2_b = (const float*)d_in[13];
    const float* ln1_g = (const float*)d_in[14];
    const float* ln1_b = (const float*)d_in[15];
    const float* ln2_g = (const float*)d_in[16];
    const float* ln2_b = (const float*)d_in[17];
    float* out = (float*)d_out;

    float *hn, *q, *k, *v, *ctx, *x1, *ff;
    float *wq, *wk, *wv, *wo, *w1, *w2;
    cudaGetSymbolAddress((void**)&hn,  g_hn);
    cudaGetSymbolAddress((void**)&q,   g_q);
    cudaGetSymbolAddress((void**)&k,   g_k);
    cudaGetSymbolAddress((void**)&v,   g_v);
    cudaGetSymbolAddress((void**)&ctx, g_ctx);
    cudaGetSymbolAddress((void**)&x1,  g_x1);
    cudaGetSymbolAddress((void**)&ff,  g_ff);
    cudaGetSymbolAddress((void**)&wq,  g_wq);
    cudaGetSymbolAddress((void**)&wk,  g_wk);
    cudaGetSymbolAddress((void**)&wv,  g_wv);
    cudaGetSymbolAddress((void**)&wo,  g_wo);
    cudaGetSymbolAddress((void**)&w1,  g_w1);
    cudaGetSymbolAddress((void**)&w2,  g_w2);

    const int GSM = NSTG * 2 * GBUF * 4;            // 110592 B
    const int ASM = (3 * 64 + 4 * 16) * ALDS * 4;   // 69632 B
    cudaFuncSetAttribute(gemm_tf32<0>, cudaFuncAttributeMaxDynamicSharedMemorySize, GSM);
    cudaFuncSetAttribute(gemm_tf32<1>, cudaFuncAttributeMaxDynamicSharedMemorySize, GSM);
    cudaFuncSetAttribute(gemm_tf32<2>, cudaFuncAttributeMaxDynamicSharedMemorySize, GSM);
    cudaFuncSetAttribute(attn_mma,     cudaFuncAttributeMaxDynamicSharedMemorySize, ASM);

    dim3 grid_d (DM  / 128, NROWS / 128);   // (8, 32)
    dim3 grid_ff(DFF / 128, NROWS / 128);   // (32, 32)

    // weight pre-rounding (rna -> tf32)
    const int n1 = DM * DM / 4, n2 = DFF * DM / 4;
    round_w<<<(n1 + 255) / 256, 256>>>(wq_w, wq, n1);
    round_w<<<(n1 + 255) / 256, 256>>>(wk_w, wk, n1);
    round_w<<<(n1 + 255) / 256, 256>>>(wv_w, wv, n1);
    round_w<<<(n1 + 255) / 256, 256>>>(wo_w, wo, n1);
    round_w<<<(n2 + 255) / 256, 256>>>(fc1_w, w1, n2);
    round_w<<<(n2 + 255) / 256, 256>>>(fc2_w, w2, n2);

    ln_kernel<<<NROWS, 256>>>(x, ln1_g, ln1_b, hn);
    gemm_tf32<0><<<grid_d, 256, GSM>>>(hn, wq, wq_b, nullptr, q, NROWS, DM, DM);
    gemm_tf32<0><<<grid_d, 256, GSM>>>(hn, wk, wk_b, nullptr, k, NROWS, DM, DM);
    gemm_tf32<0><<<grid_d, 256, GSM>>>(hn, wv, wv_b, nullptr, v, NROWS, DM, DM);
    attn_mma<<<dim3(TSEQ / 64, NH, BZ), 128, ASM>>>(q, k, v, ctx);
    gemm_tf32<1><<<grid_d, 256, GSM>>>(ctx, wo, wo_b, x, x1, NROWS, DM, DM);
    ln_kernel<<<NROWS, 256>>>(x1, ln2_g, ln2_b, hn);
    gemm_tf32<2><<<grid_ff, 256, GSM>>>(hn, w1, fc1_b, nullptr, ff, NROWS, DFF, DM);
    gemm_tf32<1><<<grid_d, 256, GSM>>>(ff, w2, fc2_b, x1, out, NROWS, DM, DFF);
}

// round 10
// speedup vs baseline: 1.2570x; 1.2570x over previous
#include <cuda_runtime.h>
#include <math.h>

#define BZ 2
#define TSEQ 2048
#define DM 1024
#define NH 16
#define DH 64
#define DFF 4096
#define NROWS (BZ * TSEQ)   /* 4096 */

// ---------------- scratch (device globals; no allocation allowed) ----------
__device__ float g_hn [(size_t)NROWS * DM];
__device__ float g_q  [(size_t)NROWS * DM];
__device__ float g_k  [(size_t)NROWS * DM];
__device__ float g_v  [(size_t)NROWS * DM];
__device__ float g_ctx[(size_t)NROWS * DM];
__device__ float g_x1 [(size_t)NROWS * DM];
__device__ float g_ff [(size_t)NROWS * DFF];

// ---------------- helpers --------------------------------------------------
__device__ __forceinline__ unsigned f2tf(float x)
{
    unsigned u;
    asm("cvt.rna.tf32.f32 %0, %1;" : "=r"(u) : "f"(x));
    return u;
}
__device__ __forceinline__ float f2tff(float x) { return __uint_as_float(f2tf(x)); }

__device__ __forceinline__ void mma_tf32(float c[4], const unsigned a[4], const unsigned b[2])
{
    asm volatile(
        "mma.sync.aligned.m16n8k8.row.col.f32.tf32.tf32.f32 "
        "{%0,%1,%2,%3}, {%4,%5,%6,%7}, {%8,%9}, {%0,%1,%2,%3};\n"
        : "+f"(c[0]), "+f"(c[1]), "+f"(c[2]), "+f"(c[3])
        : "r"(a[0]), "r"(a[1]), "r"(a[2]), "r"(a[3]), "r"(b[0]), "r"(b[1]));
}

__device__ __forceinline__ void cp16(unsigned dst, const void* src)
{
    asm volatile("cp.async.cg.shared.global [%0], [%1], 16;\n" :: "r"(dst), "l"(src));
}
__device__ __forceinline__ void cp_commit() { asm volatile("cp.async.commit_group;\n"); }
template<int N>
__device__ __forceinline__ void cp_wait() { asm volatile("cp.async.wait_group %0;\n" :: "n"(N)); }

// ---------------- layernorm: one block per row, 256 threads ---------------
// output rounded to tf32 (rna) — it is only ever consumed as GEMM A.
__global__ void ln_kernel(const float* __restrict__ x,
                          const float* __restrict__ gam,
                          const float* __restrict__ bet,
                          float* __restrict__ y)
{
    int row = blockIdx.x;
    int tid = threadIdx.x;
    const float4* xr = (const float4*)(x + (size_t)row * DM);
    float4 v = xr[tid];

    __shared__ float sh[8];
    __shared__ float bc[2];

    float s = v.x + v.y + v.z + v.w;
    #pragma unroll
    for (int o = 16; o > 0; o >>= 1) s += __shfl_xor_sync(0xffffffffu, s, o);
    if ((tid & 31) == 0) sh[tid >> 5] = s;
    __syncthreads();
    if (tid == 0) {
        float t = 0.f;
        #pragma unroll
        for (int i = 0; i < 8; i++) t += sh[i];
        bc[0] = t * (1.0f / DM);
    }
    __syncthreads();
    float mu = bc[0];

    float4 d = make_float4(v.x - mu, v.y - mu, v.z - mu, v.w - mu);
    float sq = d.x * d.x + d.y * d.y + d.z * d.z + d.w * d.w;
    #pragma unroll
    for (int o = 16; o > 0; o >>= 1) sq += __shfl_xor_sync(0xffffffffu, sq, o);
    __syncthreads();
    if ((tid & 31) == 0) sh[tid >> 5] = sq;
    __syncthreads();
    if (tid == 0) {
        float t = 0.f;
        #pragma unroll
        for (int i = 0; i < 8; i++) t += sh[i];
        bc[1] = rsqrtf(t * (1.0f / DM) + 1e-5f);
    }
    __syncthreads();
    float rstd = bc[1];

    float4 gv = ((const float4*)gam)[tid];
    float4 bv = ((const float4*)bet)[tid];
    float4 o4;
    o4.x = f2tff(d.x * rstd * gv.x + bv.x);
    o4.y = f2tff(d.y * rstd * gv.y + bv.y);
    o4.z = f2tff(d.z * rstd * gv.z + bv.z);
    o4.w = f2tff(d.w * rstd * gv.w + bv.w);
    ((float4*)(y + (size_t)row * DM))[tid] = o4;
}

// ---------------- tf32 GEMM-NT, 2-stage cp.async, single-buffer frags -----
// C[N,O] = A[N,K] @ W[O,K]^T
// A is tf32-pre-rounded by its producer kernel; W is raw fp32 and gets
// cvt.rna on the 8 B-fragment regs per k-slice (negligible ALU).
// EPI: 0 = +bias, round tf32 (QKV)   1 = +bias+res (fp32 out)
//      2 = +bias+gelu, round tf32 (fc1)
// 128x128 tile, BK=32, 256 thr = 8 warps (2M x 4N), warp 64x32, m16n8k8.
#define GLDS 36
#define GBUF (128 * GLDS)
#define NSTG 2

template<int EPI>
__global__ void __launch_bounds__(256, 2) gemm_tf32(const float* __restrict__ A,
                                                    const float* __restrict__ W,
                                                    const float* __restrict__ bias,
                                                    const float* __restrict__ res,
                                                    float* __restrict__ C,
                                                    int N, int O, int K)
{
    extern __shared__ unsigned smem_g[];
    unsigned* Ab = smem_g;                  // [NSTG][128][GLDS]
    unsigned* Wb = smem_g + NSTG * GBUF;

    int tid  = threadIdx.x;
    int warp = tid >> 5;
    int lane = tid & 31;
    int g = lane >> 2;
    int t = lane & 3;
    int m0  = (warp >> 2) * 64;
    int n0w = (warp & 3) * 32;
    int bn = blockIdx.y * 128;
    int bo = blockIdx.x * 128;

    float acc[4][4][4];
    #pragma unroll
    for (int mi = 0; mi < 4; mi++)
        #pragma unroll
        for (int nj = 0; nj < 4; nj++)
            #pragma unroll
            for (int c = 0; c < 4; c++) acc[mi][nj][c] = 0.f;

    unsigned abase = (unsigned)__cvta_generic_to_shared(Ab);
    unsigned wbase = (unsigned)__cvta_generic_to_shared(Wb);

    // chunk mapping (verified in the 1210us kernel): 1024 16B chunks per
    // matrix per stage; chunk = tid + i*256 -> row = chunk>>3, c = chunk&7.
    // 8 consecutive threads cover one full 128B row.
    #define STAGE_LOAD(s, k0)                                                   \
    {                                                                           \
        _Pragma("unroll")                                                       \
        for (int i = 0; i < 4; i++) {                                           \
            int chunk = tid + i * 256;                                          \
            int row = chunk >> 3;                                               \
            int c   = chunk & 7;                                                \
            unsigned off = ((s) * GBUF + row * GLDS + c * 4) * 4u;              \
            cp16(abase + off, A + (size_t)(bn + row) * K + (k0) + c * 4);       \
            cp16(wbase + off, W + (size_t)(bo + row) * K + (k0) + c * 4);       \
        }                                                                       \
        cp_commit();                                                            \
    }

    int ktiles = K >> 5;
    STAGE_LOAD(0, 0)
    if (ktiles > 1) STAGE_LOAD(1, 32)

    for (int kt = 0; kt < ktiles; kt++) {
        // groups in flight before wait = min(2, ktiles - kt)
        if (kt + 1 < ktiles) cp_wait<1>(); else cp_wait<0>();
        __syncthreads();                    // stage s fully visible

        int s = kt & 1;
        const unsigned* As = Ab + s * GBUF;
        const unsigned* Ws = Wb + s * GBUF;

        #pragma unroll
        for (int ks = 0; ks < 32; ks += 8) {
            unsigned af[4][4], bf[4][2];
            #pragma unroll
            for (int mi = 0; mi < 4; mi++) {
                int r = m0 + mi * 16 + g;
                af[mi][0] = As[r * GLDS + ks + t];
                af[mi][1] = As[(r + 8) * GLDS + ks + t];
                af[mi][2] = As[r * GLDS + ks + t + 4];
                af[mi][3] = As[(r + 8) * GLDS + ks + t + 4];
            }
            #pragma unroll
            for (int nj = 0; nj < 4; nj++) {
                int r = n0w + nj * 8 + g;
                // W is raw fp32: round the fragment (rna) before the mma.
                bf[nj][0] = f2tf(__uint_as_float(Ws[r * GLDS + ks + t]));
                bf[nj][1] = f2tf(__uint_as_float(Ws[r * GLDS + ks + t + 4]));
            }
            #pragma unroll
            for (int mi = 0; mi < 4; mi++)
                #pragma unroll
                for (int nj = 0; nj < 4; nj++)
                    mma_tf32(acc[mi][nj], af[mi], bf[nj]);
        }

        __syncthreads();                    // all reads of stage s done
        if (kt + 2 < ktiles) {
            STAGE_LOAD(s, (kt + 2) * 32)    // safe: stage s no longer read
        }
    }

    #pragma unroll
    for (int mi = 0; mi < 4; mi++) {
        #pragma unroll
        for (int rr = 0; rr < 2; rr++) {
            int n = bn + m0 + mi * 16 + g + rr * 8;
            #pragma unroll
            for (int nj = 0; nj < 4; nj++) {
                int o = bo + n0w + nj * 8 + t * 2;
                float c0 = acc[mi][nj][rr * 2 + 0] + bias[o];
                float c1 = acc[mi][nj][rr * 2 + 1] + bias[o + 1];
                if (EPI == 1) {
                    float2 rv = *(const float2*)(res + (size_t)n * O + o);
                    c0 += rv.x; c1 += rv.y;
                }
                if (EPI == 2) {
                    c0 = 0.5f * c0 * (1.0f + erff(c0 * 0.70710678118654752f));
                    c1 = 0.5f * c1 * (1.0f + erff(c1 * 0.70710678118654752f));
                }
                if (EPI == 0 || EPI == 2) { c0 = f2tff(c0); c1 = f2tff(c1); }
                *(float2*)(C + (size_t)n * O + o) = make_float2(c0, c1);
            }
        }
    }
}

// ---------------- FA2 attention, tf32 mma, 64x64 tiles, 128 threads -------
#define ALDS 68

__global__ void __launch_bounds__(128) attn_mma(const float* __restrict__ Q,
                                                const float* __restrict__ K,
                                                const float* __restrict__ V,
                                                float* __restrict__ O)
{
    extern __shared__ unsigned sm_a[];
    unsigned* Qs = sm_a;                    // [64][ALDS]
    unsigned* Ks = Qs + 64 * ALDS;
    unsigned* Vt = Ks + 64 * ALDS;          // transposed [d][key]
    unsigned* Ps = Vt + 64 * ALDS;          // [4][16][ALDS]

    int tid  = threadIdx.x;
    int warp = tid >> 5;
    int lane = tid & 31;
    int g = lane >> 2;
    int t = lane & 3;
    int qt = blockIdx.x, h = blockIdx.y, b = blockIdx.z;
    int q0 = qt * 64;
    int wm = warp * 16;

    {
        int r = tid >> 1, half = tid & 1;
        const float* Qb = Q + (size_t)(b * TSEQ + q0 + r) * DM + h * DH + half * 32;
        #pragma unroll
        for (int c = 0; c < 8; c++) {
            float4 v = *(const float4*)(Qb + c * 4);
            int d = half * 32 + c * 4;
            Qs[r * ALDS + d + 0] = __float_as_uint(v.x * 0.125f);
            Qs[r * ALDS + d + 1] = __float_as_uint(v.y * 0.125f);
            Qs[r * ALDS + d + 2] = __float_as_uint(v.z * 0.125f);
            Qs[r * ALDS + d + 3] = __float_as_uint(v.w * 0.125f);
        }
    }

    float mrow[2] = { -1e30f, -1e30f };
    float lrow[2] = { 0.f, 0.f };
    float o[8][4];
    #pragma unroll
    for (int nj = 0; nj < 8; nj++)
        #pragma unroll
        for (int c = 0; c < 4; c++) o[nj][c] = 0.f;

    for (int kt = 0; kt <= qt; kt++) {
        __syncthreads();
        {
            int kr = tid >> 1, half = tid & 1;
            const float* Kb = K + (size_t)(b * TSEQ + kt * 64 + kr) * DM + h * DH + half * 32;
            const float* Vb = V + (size_t)(b * TSEQ + kt * 64 + kr) * DM + h * DH + half * 32;
            #pragma unroll
            for (int c = 0; c < 8; c++) {
                float4 kv = *(const float4*)(Kb + c * 4);
                float4 vv = *(const float4*)(Vb + c * 4);
                int d = half * 32 + c * 4;
                Ks[kr * ALDS + d + 0] = __float_as_uint(kv.x);
                Ks[kr * ALDS + d + 1] = __float_as_uint(kv.y);
                Ks[kr * ALDS + d + 2] = __float_as_uint(kv.z);
                Ks[kr * ALDS + d + 3] = __float_as_uint(kv.w);
                Vt[(d + 0) * ALDS + kr] = __float_as_uint(vv.x);
                Vt[(d + 1) * ALDS + kr] = __float_as_uint(vv.y);
                Vt[(d + 2) * ALDS + kr] = __float_as_uint(vv.z);
                Vt[(d + 3) * ALDS + kr] = __float_as_uint(vv.w);
            }
        }
        __syncthreads();

        float s[8][4];
        #pragma unroll
        for (int nj = 0; nj < 8; nj++)
            #pragma unroll
            for (int c = 0; c < 4; c++) s[nj][c] = 0.f;

        #pragma unroll
        for (int ks = 0; ks < 8; ks++) {
            unsigned a[4];
            a[0] = Qs[(wm + g) * ALDS + ks * 8 + t];
            a[1] = Qs[(wm + g + 8) * ALDS + ks * 8 + t];
            a[2] = Qs[(wm + g) * ALDS + ks * 8 + t + 4];
            a[3] = Qs[(wm + g + 8) * ALDS + ks * 8 + t + 4];
            #pragma unroll
            for (int nj = 0; nj < 8; nj++) {
                unsigned bfr[2];
                bfr[0] = Ks[(nj * 8 + g) * ALDS + ks * 8 + t];
                bfr[1] = Ks[(nj * 8 + g) * ALDS + ks * 8 + t + 4];
                mma_tf32(s[nj], a, bfr);
            }
        }

        if (kt == qt) {
            #pragma unroll
            for (int nj = 0; nj < 8; nj++)
                #pragma unroll
                for (int c = 0; c < 4; c++) {
                    int col = nj * 8 + 2 * t + (c & 1);
                    int row = wm + g + ((c >> 1) << 3);
                    if (col > row) s[nj][c] = -1e30f;
                }
        }

        #pragma unroll
        for (int rr = 0; rr < 2; rr++) {
            float rm = -1e30f;
            #pragma unroll
            for (int nj = 0; nj < 8; nj++)
                rm = fmaxf(rm, fmaxf(s[nj][rr * 2], s[nj][rr * 2 + 1]));
            rm = fmaxf(rm, __shfl_xor_sync(0xffffffffu, rm, 1));
            rm = fmaxf(rm, __shfl_xor_sync(0xffffffffu, rm, 2));
            float mn = fmaxf(mrow[rr], rm);
            float alpha = __expf(mrow[rr] - mn);
            float rs = 0.f;
            int prow = wm * ALDS + (g + rr * 8) * ALDS;
            #pragma unroll
            for (int nj = 0; nj < 8; nj++) {
                float p0 = __expf(s[nj][rr * 2] - mn);
                float p1 = __expf(s[nj][rr * 2 + 1] - mn);
                Ps[prow + nj * 8 + 2 * t]     = f2tf(p0);
                Ps[prow + nj * 8 + 2 * t + 1] = f2tf(p1);
                rs += p0 + p1;
            }
            rs += __shfl_xor_sync(0xffffffffu, rs, 1);
            rs += __shfl_xor_sync(0xffffffffu, rs, 2);
            lrow[rr] = lrow[rr] * alpha + rs;
            mrow[rr] = mn;
            #pragma unroll
            for (int nj = 0; nj < 8; nj++) {
                o[nj][rr * 2]     *= alpha;
                o[nj][rr * 2 + 1] *= alpha;
            }
        }
        __syncwarp();

        #pragma unroll
        for (int ks = 0; ks < 8; ks++) {
            unsigned a[4];
            int pb = wm * ALDS;
            a[0] = Ps[pb + g * ALDS + ks * 8 + t];
            a[1] = Ps[pb + (g + 8) * ALDS + ks * 8 + t];
            a[2] = Ps[pb + g * ALDS + ks * 8 + t + 4];
            a[3] = Ps[pb + (g + 8) * ALDS + ks * 8 + t + 4];
            #pragma unroll
            for (int nj = 0; nj < 8; nj++) {
                unsigned bfr[2];
                bfr[0] = Vt[(nj * 8 + g) * ALDS + ks * 8 + t];
                bfr[1] = Vt[(nj * 8 + g) * ALDS + ks * 8 + t + 4];
                mma_tf32(o[nj], a, bfr);
            }
        }
    }

    #pragma unroll
    for (int rr = 0; rr < 2; rr++) {
        float inv = 1.0f / lrow[rr];
        int row = q0 + wm + g + rr * 8;
        float* Ob = O + (size_t)(b * TSEQ + row) * DM + h * DH;
        #pragma unroll
        for (int nj = 0; nj < 8; nj++) {
            float2 w = make_float2(f2tff(o[nj][rr * 2] * inv),
                                   f2tff(o[nj][rr * 2 + 1] * inv));
            *(float2*)(Ob + nj * 8 + 2 * t) = w;
        }
    }
}

// ---------------- launch -------------------------------------------------
extern "C" void kernel_launch(void* const* d_in, const int* in_sizes, int n_in,
                              void* d_out, int out_size)
{
    const float* x    = (const float*)d_in[0];
    // d_in[1] = causal mask (static, ignored)
    const float* wq_w = (const float*)d_in[2];
    const float* wq_b = (const float*)d_in[3];
    const float* wk_w = (const float*)d_in[4];
    const float* wk_b = (const float*)d_in[5];
    const float* wv_w = (const float*)d_in[6];
    const float* wv_b = (const float*)d_in[7];
    const float* wo_w = (const float*)d_in[8];
    const float* wo_b = (const float*)d_in[9];
    const float* fc1_w = (const float*)d_in[10];
    const float* fc1_b = (const float*)d_in[11];
    const float* fc2_w = (const float*)d_in[12];
    const float* fc2_b = (const float*)d_in[13];
    const float* ln1_g = (const float*)d_in[14];
    const float* ln1_b = (const float*)d_in[15];
    const float* ln2_g = (const float*)d_in[16];
    const float* ln2_b = (const float*)d_in[17];
    float* out = (float*)d_out;

    float *hn, *q, *k, *v, *ctx, *x1, *ff;
    cudaGetSymbolAddress((void**)&hn,  g_hn);
    cudaGetSymbolAddress((void**)&q,   g_q);
    cudaGetSymbolAddress((void**)&k,   g_k);
    cudaGetSymbolAddress((void**)&v,   g_v);
    cudaGetSymbolAddress((void**)&ctx, g_ctx);
    cudaGetSymbolAddress((void**)&x1,  g_x1);
    cudaGetSymbolAddress((void**)&ff,  g_ff);

    const int GSM = NSTG * 2 * GBUF * 4;            // 73728 B
    const int ASM = (3 * 64 + 4 * 16) * ALDS * 4;   // 69632 B
    cudaFuncSetAttribute(gemm_tf32<0>, cudaFuncAttributeMaxDynamicSharedMemorySize, GSM);
    cudaFuncSetAttribute(gemm_tf32<1>, cudaFuncAttributeMaxDynamicSharedMemorySize, GSM);
    cudaFuncSetAttribute(gemm_tf32<2>, cudaFuncAttributeMaxDynamicSharedMemorySize, GSM);
    cudaFuncSetAttribute(attn_mma,     cudaFuncAttributeMaxDynamicSharedMemorySize, ASM);

    dim3 grid_d (DM  / 128, NROWS / 128);   // (8, 32)
    dim3 grid_ff(DFF / 128, NROWS / 128);   // (32, 32)

    ln_kernel<<<NROWS, 256>>>(x, ln1_g, ln1_b, hn);
    gemm_tf32<0><<<grid_d, 256, GSM>>>(hn, wq_w, wq_b, nullptr, q, NROWS, DM, DM);
    gemm_tf32<0><<<grid_d, 256, GSM>>>(hn, wk_w, wk_b, nullptr, k, NROWS, DM, DM);
    gemm_tf32<0><<<grid_d, 256, GSM>>>(hn, wv_w, wv_b, nullptr, v, NROWS, DM, DM);
    attn_mma<<<dim3(TSEQ / 64, NH, BZ), 128, ASM>>>(q, k, v, ctx);
    gemm_tf32<1><<<grid_d, 256, GSM>>>(ctx, wo_w, wo_b, x, x1, NROWS, DM, DM);
    ln_kernel<<<NROWS, 256>>>(x1, ln2_g, ln2_b, hn);
    gemm_tf32<2><<<grid_ff, 256, GSM>>>(hn, fc1_w, fc1_b, nullptr, ff, NROWS, DFF, DM);
    gemm_tf32<1><<<grid_d, 256, GSM>>>(ff, fc2_w, fc2_b, x1, out, NROWS, DM, DFF);
}

// round 15
// speedup vs baseline: 2.4987x; 1.9879x over previous
#include <cuda_runtime.h>
#include <cuda_fp16.h>
#include <math.h>
#include <stdint.h>

#define BZ 2
#define TSEQ 2048
#define DM 1024
#define NH 16
#define DH 64
#define DFF 4096
#define NROWS (BZ * TSEQ)   /* 4096 */

// ---------------- scratch (device globals; no allocation allowed) ----------
__device__ __half g_hn [(size_t)NROWS * DM];
__device__ __half g_q  [(size_t)NROWS * DM];
__device__ __half g_k  [(size_t)NROWS * DM];
__device__ __half g_v  [(size_t)NROWS * DM];
__device__ __half g_ctx[(size_t)NROWS * DM];
__device__ float  g_x1 [(size_t)NROWS * DM];
__device__ __half g_ff [(size_t)NROWS * DFF];
// fp16 weights
__device__ __half g_wq [(size_t)DM * DM];
__device__ __half g_wk [(size_t)DM * DM];
__device__ __half g_wv [(size_t)DM * DM];
__device__ __half g_wo [(size_t)DM * DM];
__device__ __half g_w1 [(size_t)DFF * DM];
__device__ __half g_w2 [(size_t)DM * DFF];

// ---------------- helpers --------------------------------------------------
__device__ __forceinline__ void mma_f16(float c[4], const unsigned a[4], const unsigned b[2])
{
    asm volatile(
        "mma.sync.aligned.m16n8k16.row.col.f32.f16.f16.f32 "
        "{%0,%1,%2,%3}, {%4,%5,%6,%7}, {%8,%9}, {%0,%1,%2,%3};\n"
        : "+f"(c[0]), "+f"(c[1]), "+f"(c[2]), "+f"(c[3])
        : "r"(a[0]), "r"(a[1]), "r"(a[2]), "r"(a[3]), "r"(b[0]), "r"(b[1]));
}

__device__ __forceinline__ void cp16(unsigned dst, const void* src)
{
    asm volatile("cp.async.cg.shared.global [%0], [%1], 16;\n" :: "r"(dst), "l"(src));
}
__device__ __forceinline__ void cp_commit() { asm volatile("cp.async.commit_group;\n"); }
template<int N>
__device__ __forceinline__ void cp_wait() { asm volatile("cp.async.wait_group %0;\n" :: "n"(N)); }

// ---------------- weight conversion fp32 -> fp16 (rn) ----------------------
__global__ void cvt_h(const float* __restrict__ src, __half* __restrict__ dst, int n4)
{
    int i = blockIdx.x * 256 + threadIdx.x;
    if (i >= n4) return;
    float4 v = ((const float4*)src)[i];
    ((__half2*)dst)[2 * i]     = __floats2half2_rn(v.x, v.y);
    ((__half2*)dst)[2 * i + 1] = __floats2half2_rn(v.z, v.w);
}

// ---------------- layernorm: one block per row, 256 threads, fp16 out -----
__global__ void ln_kernel(const float* __restrict__ x,
                          const float* __restrict__ gam,
                          const float* __restrict__ bet,
                          __half* __restrict__ y)
{
    int row = blockIdx.x;
    int tid = threadIdx.x;
    const float4* xr = (const float4*)(x + (size_t)row * DM);
    float4 v = xr[tid];

    __shared__ float sh[8];
    __shared__ float bc[2];

    float s = v.x + v.y + v.z + v.w;
    #pragma unroll
    for (int o = 16; o > 0; o >>= 1) s += __shfl_xor_sync(0xffffffffu, s, o);
    if ((tid & 31) == 0) sh[tid >> 5] = s;
    __syncthreads();
    if (tid == 0) {
        float t = 0.f;
        #pragma unroll
        for (int i = 0; i < 8; i++) t += sh[i];
        bc[0] = t * (1.0f / DM);
    }
    __syncthreads();
    float mu = bc[0];

    float4 d = make_float4(v.x - mu, v.y - mu, v.z - mu, v.w - mu);
    float sq = d.x * d.x + d.y * d.y + d.z * d.z + d.w * d.w;
    #pragma unroll
    for (int o = 16; o > 0; o >>= 1) sq += __shfl_xor_sync(0xffffffffu, sq, o);
    __syncthreads();
    if ((tid & 31) == 0) sh[tid >> 5] = sq;
    __syncthreads();
    if (tid == 0) {
        float t = 0.f;
        #pragma unroll
        for (int i = 0; i < 8; i++) t += sh[i];
        bc[1] = rsqrtf(t * (1.0f / DM) + 1e-5f);
    }
    __syncthreads();
    float rstd = bc[1];

    float4 gv = ((const float4*)gam)[tid];
    float4 bv = ((const float4*)bet)[tid];
    __half2 h0 = __floats2half2_rn(d.x * rstd * gv.x + bv.x, d.y * rstd * gv.y + bv.y);
    __half2 h1 = __floats2half2_rn(d.z * rstd * gv.z + bv.z, d.w * rstd * gv.w + bv.w);
    __half2* yr = (__half2*)(y + (size_t)row * DM);
    yr[2 * tid]     = h0;
    yr[2 * tid + 1] = h1;
}

// ---------------- fp16 GEMM-NT, 2-stage cp.async --------------------------
// C[N,O] = A[N,K] @ W[O,K]^T, fp16 operands, fp32 accumulate.
// EPI: 0 = +bias -> fp16 C   1 = +bias+res -> fp32 C   2 = +bias+gelu -> fp16 C
// 128x128 tile, BK=64 halves, 256 thr = 8 warps (2M x 4N), warp 64x32, m16n8k16.
#define HLDS 36
#define GBUF (128 * HLDS)

template<int EPI>
__global__ void __launch_bounds__(256, 2) gemm_h(const __half* __restrict__ A,
                                                 const __half* __restrict__ W,
                                                 const float* __restrict__ bias,
                                                 const float* __restrict__ res,
                                                 void* __restrict__ Cv,
                                                 int N, int O, int K)
{
    extern __shared__ unsigned smem_g[];
    unsigned* Ab = smem_g;                  // [2][128][HLDS] half2 words
    unsigned* Wb = smem_g + 2 * GBUF;

    int tid  = threadIdx.x;
    int warp = tid >> 5;
    int lane = tid & 31;
    int g = lane >> 2;
    int t = lane & 3;
    int m0  = (warp >> 2) * 64;
    int n0w = (warp & 3) * 32;
    int bn = blockIdx.y * 128;
    int bo = blockIdx.x * 128;

    float acc[4][4][4];
    #pragma unroll
    for (int mi = 0; mi < 4; mi++)
        #pragma unroll
        for (int nj = 0; nj < 4; nj++)
            #pragma unroll
            for (int c = 0; c < 4; c++) acc[mi][nj][c] = 0.f;

    unsigned abase = (unsigned)__cvta_generic_to_shared(Ab);
    unsigned wbase = (unsigned)__cvta_generic_to_shared(Wb);

    #define STAGE_LOAD(s, kt)                                                   \
    {                                                                           \
        _Pragma("unroll")                                                       \
        for (int i = 0; i < 4; i++) {                                           \
            int chunk = tid + i * 256;                                          \
            int row = chunk >> 3;                                               \
            int c   = chunk & 7;                                                \
            unsigned off = ((s) * GBUF + row * HLDS + c * 4) * 4u;              \
            cp16(abase + off, A + (size_t)(bn + row) * K + (size_t)(kt) * 64 + c * 8); \
            cp16(wbase + off, W + (size_t)(bo + row) * K + (size_t)(kt) * 64 + c * 8); \
        }                                                                       \
        cp_commit();                                                            \
    }

    int ktiles = K >> 6;
    STAGE_LOAD(0, 0)
    if (ktiles > 1) STAGE_LOAD(1, 1)

    for (int kt = 0; kt < ktiles; kt++) {
        if (kt + 1 < ktiles) cp_wait<1>(); else cp_wait<0>();
        __syncthreads();

        int s = kt & 1;
        const unsigned* As = Ab + s * GBUF;
        const unsigned* Ws = Wb + s * GBUF;

        #pragma unroll
        for (int ks = 0; ks < 4; ks++) {
            int base = ks * 8;
            unsigned af[4][4], bf[4][2];
            #pragma unroll
            for (int mi = 0; mi < 4; mi++) {
                int r = m0 + mi * 16 + g;
                af[mi][0] = As[r * HLDS + base + t];
                af[mi][1] = As[(r + 8) * HLDS + base + t];
                af[mi][2] = As[r * HLDS + base + t + 4];
                af[mi][3] = As[(r + 8) * HLDS + base + t + 4];
            }
            #pragma unroll
            for (int nj = 0; nj < 4; nj++) {
                int rn = n0w + nj * 8 + g;
                bf[nj][0] = Ws[rn * HLDS + base + t];
                bf[nj][1] = Ws[rn * HLDS + base + t + 4];
            }
            #pragma unroll
            for (int mi = 0; mi < 4; mi++)
                #pragma unroll
                for (int nj = 0; nj < 4; nj++)
                    mma_f16(acc[mi][nj], af[mi], bf[nj]);
        }

        __syncthreads();
        if (kt + 2 < ktiles) {
            STAGE_LOAD(s, kt + 2)
        }
    }

    #pragma unroll
    for (int mi = 0; mi < 4; mi++) {
        #pragma unroll
        for (int rr = 0; rr < 2; rr++) {
            int n = bn + m0 + mi * 16 + g + rr * 8;
            #pragma unroll
            for (int nj = 0; nj < 4; nj++) {
                int o = bo + n0w + nj * 8 + t * 2;
                float c0 = acc[mi][nj][rr * 2 + 0] + bias[o];
                float c1 = acc[mi][nj][rr * 2 + 1] + bias[o + 1];
                if (EPI == 1) {
                    float2 rv = *(const float2*)(res + (size_t)n * O + o);
                    c0 += rv.x; c1 += rv.y;
                    *(float2*)((float*)Cv + (size_t)n * O + o) = make_float2(c0, c1);
                } else {
                    if (EPI == 2) {
                        c0 = 0.5f * c0 * (1.0f + erff(c0 * 0.70710678118654752f));
                        c1 = 0.5f * c1 * (1.0f + erff(c1 * 0.70710678118654752f));
                    }
                    *(__half2*)((__half*)Cv + (size_t)n * O + o) = __floats2half2_rn(c0, c1);
                }
            }
        }
    }
}

// ---------------- FA2 attention, fp16 mma, 64x64 tiles, 128 threads -------
#define AH 36   /* u32 (half2) stride per 64-half row */

__global__ void __launch_bounds__(128) attn_mma(const __half* __restrict__ Q,
                                                const __half* __restrict__ K,
                                                const __half* __restrict__ V,
                                                __half* __restrict__ O)
{
    extern __shared__ unsigned sm_a[];
    unsigned* Qs = sm_a;                    // [64 q][AH]   pairs along d
    unsigned* Ks = Qs + 64 * AH;            // [64 key][AH] pairs along d
    unsigned* Vt = Ks + 64 * AH;            // [64 d][AH]   pairs along key
    unsigned* Ps = Vt + 64 * AH;            // [64 q][AH]   pairs along key

    int tid  = threadIdx.x;
    int warp = tid >> 5;
    int lane = tid & 31;
    int g = lane >> 2;
    int t = lane & 3;
    int qt = blockIdx.x, h = blockIdx.y, b = blockIdx.z;
    int q0 = qt * 64;
    int wm = warp * 16;

    {
        int r = tid >> 1, hf = tid & 1;
        const uint4* Qb = (const uint4*)(Q + (size_t)(b * TSEQ + q0 + r) * DM + h * DH + hf * 32);
        #pragma unroll
        for (int i = 0; i < 4; i++) {
            uint4 v = Qb[i];
            int p = r * AH + hf * 16 + i * 4;
            Qs[p + 0] = v.x; Qs[p + 1] = v.y; Qs[p + 2] = v.z; Qs[p + 3] = v.w;
        }
    }

    float mrow[2] = { -1e30f, -1e30f };
    float lrow[2] = { 0.f, 0.f };
    float o[8][4];
    #pragma unroll
    for (int nj = 0; nj < 8; nj++)
        #pragma unroll
        for (int c = 0; c < 4; c++) o[nj][c] = 0.f;

    for (int kt = 0; kt <= qt; kt++) {
        __syncthreads();
        {
            int kr = tid >> 1, hf = tid & 1;
            const uint4* Kb = (const uint4*)(K + (size_t)(b * TSEQ + kt * 64 + kr) * DM + h * DH + hf * 32);
            const uint4* Vb = (const uint4*)(V + (size_t)(b * TSEQ + kt * 64 + kr) * DM + h * DH + hf * 32);
            __half* Vth = (__half*)Vt;
            #pragma unroll
            for (int i = 0; i < 4; i++) {
                uint4 kv = Kb[i];
                int p = kr * AH + hf * 16 + i * 4;
                Ks[p + 0] = kv.x; Ks[p + 1] = kv.y; Ks[p + 2] = kv.z; Ks[p + 3] = kv.w;
                uint4 vv = Vb[i];
                unsigned w[4] = { vv.x, vv.y, vv.z, vv.w };
                #pragma unroll
                for (int j = 0; j < 4; j++) {
                    __half2 hh = *(__half2*)&w[j];
                    int d = hf * 32 + i * 8 + j * 2;
                    Vth[(size_t)d * (2 * AH) + kr]       = __low2half(hh);
                    Vth[(size_t)(d + 1) * (2 * AH) + kr] = __high2half(hh);
                }
            }
        }
        __syncthreads();

        float s[8][4];
        #pragma unroll
        for (int nj = 0; nj < 8; nj++)
            #pragma unroll
            for (int c = 0; c < 4; c++) s[nj][c] = 0.f;

        #pragma unroll
        for (int ks = 0; ks < 4; ks++) {
            int base = ks * 8;
            unsigned a[4];
            a[0] = Qs[(wm + g) * AH + base + t];
            a[1] = Qs[(wm + g + 8) * AH + base + t];
            a[2] = Qs[(wm + g) * AH + base + t + 4];
            a[3] = Qs[(wm + g + 8) * AH + base + t + 4];
            #pragma unroll
            for (int nj = 0; nj < 8; nj++) {
                unsigned bfr[2];
                bfr[0] = Ks[(nj * 8 + g) * AH + base + t];
                bfr[1] = Ks[(nj * 8 + g) * AH + base + t + 4];
                mma_f16(s[nj], a, bfr);
            }
        }
        #pragma unroll
        for (int nj = 0; nj < 8; nj++)
            #pragma unroll
            for (int c = 0; c < 4; c++) s[nj][c] *= 0.125f;

        if (kt == qt) {
            #pragma unroll
            for (int nj = 0; nj < 8; nj++)
                #pragma unroll
                for (int c = 0; c < 4; c++) {
                    int col = nj * 8 + 2 * t + (c & 1);
                    int row = wm + g + ((c >> 1) << 3);
                    if (col > row) s[nj][c] = -1e30f;
                }
        }

        #pragma unroll
        for (int rr = 0; rr < 2; rr++) {
            float rm = -1e30f;
            #pragma unroll
            for (int nj = 0; nj < 8; nj++)
                rm = fmaxf(rm, fmaxf(s[nj][rr * 2], s[nj][rr * 2 + 1]));
            rm = fmaxf(rm, __shfl_xor_sync(0xffffffffu, rm, 1));
            rm = fmaxf(rm, __shfl_xor_sync(0xffffffffu, rm, 2));
            float mn = fmaxf(mrow[rr], rm);
            float alpha = __expf(mrow[rr] - mn);
            float rs = 0.f;
            int prow = (wm + g + rr * 8) * AH;
            #pragma unroll
            for (int nj = 0; nj < 8; nj++) {
                float p0 = __expf(s[nj][rr * 2] - mn);
                float p1 = __expf(s[nj][rr * 2 + 1] - mn);
                __half2 ph = __floats2half2_rn(p0, p1);
                Ps[prow + nj * 4 + t] = *(unsigned*)&ph;
                rs += p0 + p1;
            }
            rs += __shfl_xor_sync(0xffffffffu, rs, 1);
            rs += __shfl_xor_sync(0xffffffffu, rs, 2);
            lrow[rr] = lrow[rr] * alpha + rs;
            mrow[rr] = mn;
            #pragma unroll
            for (int nj = 0; nj < 8; nj++) {
                o[nj][rr * 2]     *= alpha;
                o[nj][rr * 2 + 1] *= alpha;
            }
        }
        __syncwarp();

        #pragma unroll
        for (int ks = 0; ks < 4; ks++) {
            int base = ks * 8;
            unsigned a[4];
            a[0] = Ps[(wm + g) * AH + base + t];
            a[1] = Ps[(wm + g + 8) * AH + base + t];
            a[2] = Ps[(wm + g) * AH + base + t + 4];
            a[3] = Ps[(wm + g + 8) * AH + base + t + 4];
            #pragma unroll
            for (int nj = 0; nj < 8; nj++) {
                unsigned bfr[2];
                bfr[0] = Vt[(nj * 8 + g) * AH + base + t];
                bfr[1] = Vt[(nj * 8 + g) * AH + base + t + 4];
                mma_f16(o[nj], a, bfr);
            }
        }
    }

    #pragma unroll
    for (int rr = 0; rr < 2; rr++) {
        float inv = 1.0f / lrow[rr];
        int row = q0 + wm + g + rr * 8;
        __half* Ob = O + (size_t)(b * TSEQ + row) * DM + h * DH;
        #pragma unroll
        for (int nj = 0; nj < 8; nj++) {
            *(__half2*)(Ob + nj * 8 + 2 * t) =
                __floats2half2_rn(o[nj][rr * 2] * inv, o[nj][rr * 2 + 1] * inv);
        }
    }
}

// ---------------- launch -------------------------------------------------
extern "C" void kernel_launch(void* const* d_in, const int* in_sizes, int n_in,
                              void* d_out, int out_size)
{
    const float* x    = (const float*)d_in[0];
    // d_in[1] = causal mask (static, ignored)
    const float* wq_w = (const float*)d_in[2];
    const float* wq_b = (const float*)d_in[3];
    const float* wk_w = (const float*)d_in[4];
    const float* wk_b = (const float*)d_in[5];
    const float* wv_w = (const float*)d_in[6];
    const float* wv_b = (const float*)d_in[7];
    const float* wo_w = (const float*)d_in[8];
    const float* wo_b = (const float*)d_in[9];
    const float* fc1_w = (const float*)d_in[10];
    const float* fc1_b = (const float*)d_in[11];
    const float* fc2_w = (const float*)d_in[12];
    const float* fc2_b = (const float*)d_in[13];
    const float* ln1_g = (const float*)d_in[14];
    const float* ln1_b = (const float*)d_in[15];
    const float* ln2_g = (const float*)d_in[16];
    const float* ln2_b = (const float*)d_in[17];
    float* out = (float*)d_out;

    __half *hn, *q, *k, *v, *ctx, *ff;
    float *x1;
    __half *wq, *wk, *wv, *wo, *w1, *w2;
    cudaGetSymbolAddress((void**)&hn,  g_hn);
    cudaGetSymbolAddress((void**)&q,   g_q);
    cudaGetSymbolAddress((void**)&k,   g_k);
    cudaGetSymbolAddress((void**)&v,   g_v);
    cudaGetSymbolAddress((void**)&ctx, g_ctx);
    cudaGetSymbolAddress((void**)&x1,  g_x1);
    cudaGetSymbolAddress((void**)&ff,  g_ff);
    cudaGetSymbolAddress((void**)&wq,  g_wq);
    cudaGetSymbolAddress((void**)&wk,  g_wk);
    cudaGetSymbolAddress((void**)&wv,  g_wv);
    cudaGetSymbolAddress((void**)&wo,  g_wo);
    cudaGetSymbolAddress((void**)&w1,  g_w1);
    cudaGetSymbolAddress((void**)&w2,  g_w2);

    const int GSM = 2 * 2 * GBUF * 4;               // 73728 B
    const int ASM = 4 * 64 * AH * 4;                // 36864 B
    cudaFuncSetAttribute(gemm_h<0>, cudaFuncAttributeMaxDynamicSharedMemorySize, GSM);
    cudaFuncSetAttribute(gemm_h<1>, cudaFuncAttributeMaxDynamicSharedMemorySize, GSM);
    cudaFuncSetAttribute(gemm_h<2>, cudaFuncAttributeMaxDynamicSharedMemorySize, GSM);
    cudaFuncSetAttribute(attn_mma,  cudaFuncAttributeMaxDynamicSharedMemorySize, ASM);

    dim3 grid_d (DM  / 128, NROWS / 128);   // (8, 32)
    dim3 grid_ff(DFF / 128, NROWS / 128);   // (32, 32)

    const int n1 = DM * DM / 4, n2 = DFF * DM / 4;
    cvt_h<<<(n1 + 255) / 256, 256>>>(wq_w, wq, n1);
    cvt_h<<<(n1 + 255) / 256, 256>>>(wk_w, wk, n1);
    cvt_h<<<(n1 + 255) / 256, 256>>>(wv_w, wv, n1);
    cvt_h<<<(n1 + 255) / 256, 256>>>(wo_w, wo, n1);
    cvt_h<<<(n2 + 255) / 256, 256>>>(fc1_w, w1, n2);
    cvt_h<<<(n2 + 255) / 256, 256>>>(fc2_w, w2, n2);

    ln_kernel<<<NROWS, 256>>>(x, ln1_g, ln1_b, hn);
    gemm_h<0><<<grid_d, 256, GSM>>>(hn, wq, wq_b, nullptr, q, NROWS, DM, DM);
    gemm_h<0><<<grid_d, 256, GSM>>>(hn, wk, wk_b, nullptr, k, NROWS, DM, DM);
    gemm_h<0><<<grid_d, 256, GSM>>>(hn, wv, wv_b, nullptr, v, NROWS, DM, DM);
    attn_mma<<<dim3(TSEQ / 64, NH, BZ), 128, ASM>>>(q, k, v, ctx);
    gemm_h<1><<<grid_d, 256, GSM>>>(ctx, wo, wo_b, x, x1, NROWS, DM, DM);
    ln_kernel<<<NROWS, 256>>>(x1, ln2_g, ln2_b, hn);
    gemm_h<2><<<grid_ff, 256, GSM>>>(hn, w1, fc1_b, nullptr, ff, NROWS, DFF, DM);
    gemm_h<1><<<grid_d, 256, GSM>>>(ff, w2, fc2_b, x1, out, NROWS, DM, DFF);
}